// round 12
// baseline (speedup 1.0000x reference)
#include <cuda_runtime.h>
#include <cuda_fp16.h>
#include <cstdint>

// Problem constants (B=1)
#define L 768
#define C_IN 384
#define D 32          // C_OUTER
#define E 128         // C_OUT
#define EPS 1e-5f

// ---------------- scratch (no allocations allowed) ----------------
__device__ float g_right[L * D];
__device__ __align__(16) __half g_lh[L * D];   // left (fp16)

// ================= PTX helpers =================
__device__ __forceinline__ uint32_t smem_u32(const void* p) {
    uint32_t a;
    asm("{ .reg .u64 t; cvta.to.shared.u64 t, %1; cvt.u32.u64 %0, t; }" : "=r"(a) : "l"(p));
    return a;
}
__device__ __forceinline__ void ldsm_x4(uint32_t* r, uint32_t addr) {
    asm volatile("ldmatrix.sync.aligned.m8n8.x4.shared.b16 {%0,%1,%2,%3}, [%4];"
                 : "=r"(r[0]), "=r"(r[1]), "=r"(r[2]), "=r"(r[3]) : "r"(addr));
}
__device__ __forceinline__ void mma16816(float* c, const uint32_t* a, const uint32_t* b) {
    asm volatile("mma.sync.aligned.m16n8k16.row.col.f32.f16.f16.f32 "
                 "{%0,%1,%2,%3}, {%4,%5,%6,%7}, {%8,%9}, {%0,%1,%2,%3};"
                 : "+f"(c[0]), "+f"(c[1]), "+f"(c[2]), "+f"(c[3])
                 : "r"(a[0]), "r"(a[1]), "r"(a[2]), "r"(a[3]), "r"(b[0]), "r"(b[1]));
}
#define CP_ASYNC16(dst, src) \
    asm volatile("cp.async.ca.shared.global [%0], [%1], 16;" :: "r"(dst), "l"(src) : "memory")
#define CP_COMMIT()  asm volatile("cp.async.commit_group;" ::: "memory")
#define CP_WAIT0()   asm volatile("cp.async.wait_group 0;" ::: "memory")

// ---------------- Kernel A: LayerNorm + left/right projections ----------------
__global__ void __launch_bounds__(256) ln_proj_kernel(
    const float* __restrict__ act, const float* __restrict__ mask,
    const float* __restrict__ nw, const float* __restrict__ nb,
    const float* __restrict__ wl, const float* __restrict__ bl,
    const float* __restrict__ wr, const float* __restrict__ br)
{
    __shared__ float s_norm[C_IN];
    __shared__ float warp_sum[8];
    __shared__ float bcast;
    __shared__ float red[256];

    const int l = blockIdx.x;
    const int tid = threadIdx.x;
    const int lane = tid & 31;
    const int wid = tid >> 5;
    const float* arow = act + (size_t)l * C_IN;

    const float x0 = arow[tid];
    const float x1 = (tid < C_IN - 256) ? arow[256 + tid] : 0.0f;

    float s = x0 + x1;
    #pragma unroll
    for (int o = 16; o > 0; o >>= 1) s += __shfl_xor_sync(0xffffffffu, s, o);
    if (lane == 0) warp_sum[wid] = s;
    __syncthreads();
    if (tid == 0) {
        float t = 0.f;
        #pragma unroll
        for (int w = 0; w < 8; ++w) t += warp_sum[w];
        bcast = t * (1.0f / C_IN);
    }
    __syncthreads();
    const float mu = bcast;

    const float d0 = x0 - mu;
    const float d1 = (tid < C_IN - 256) ? (x1 - mu) : 0.0f;
    float v = d0 * d0 + d1 * d1;
    #pragma unroll
    for (int o = 16; o > 0; o >>= 1) v += __shfl_xor_sync(0xffffffffu, v, o);
    if (lane == 0) warp_sum[wid] = v;
    __syncthreads();
    if (tid == 0) {
        float t = 0.f;
        #pragma unroll
        for (int w = 0; w < 8; ++w) t += warp_sum[w];
        bcast = rsqrtf(t * (1.0f / C_IN) + EPS);
    }
    __syncthreads();
    const float rstd = bcast;

    s_norm[tid] = d0 * rstd * nw[tid] + nb[tid];
    if (tid < C_IN - 256)
        s_norm[256 + tid] = d1 * rstd * nw[256 + tid] + nb[256 + tid];
    __syncthreads();

    const int oc  = tid & 63;
    const int q   = tid >> 6;
    const int col = oc & 31;
    const float* w = (oc < 32) ? wl : wr;
    float dot = 0.0f;
    const int c0 = q * (C_IN / 4);
    #pragma unroll 8
    for (int c = c0; c < c0 + C_IN / 4; ++c)
        dot += s_norm[c] * w[c * D + col];
    red[tid] = dot;
    __syncthreads();
    if (tid < 128) red[tid] += red[tid + 128];
    __syncthreads();
    if (tid < 64) {
        const float vv = red[tid] + red[tid + 64];
        const float m = mask[l];
        const float val = m * (vv + ((oc < 32) ? bl[col] : br[col]));
        if (oc < 32) g_lh[l * D + col] = __float2half_rn(val);
        else         g_right[l * D + col] = val;
    }
}

// ---------------- Kernel C: mma.sync batched GEMM (fp16, K=32) ----------------
// grid = (2 j-halves, L i), block = 256 (8 warps: 2 mw x 4 nq), 12 j-tiles of 32 rows
// A double-buffered via cp.async; B fragments hoisted; output staged through
// swizzled smem so every STG.128 writes one full 512B row (4 full lines).
#define RSTRIDE 80
#define BTILEB  10240
#define ATILEB  2560           // 32 rows x 80 B
#define SOFF_LIN   0
#define SOFF_B     512
#define SOFF_A0    (512 + BTILEB)
#define SOFF_A1    (512 + BTILEB + ATILEB)
#define SOFF_STG   (512 + BTILEB + 2 * ATILEB)       // 15872
#define SMEM_PAIR  (SOFF_STG + 32 * 512)             // 32256

__global__ void __launch_bounds__(256, 4) pair_kernel(
    const float* __restrict__ wo, const float* __restrict__ bo,
    float* __restrict__ out)
{
    extern __shared__ char smem[];
    __shared__ float r_s[D];
    const uint32_t sb = smem_u32(smem);
    const uint32_t sB = sb + SOFF_B;
    const uint32_t sStage = sb + SOFF_STG;
    float* lin_s = reinterpret_cast<float*>(smem + SOFF_LIN);

    const int tid = threadIdx.x;
    const int wid = tid >> 5;
    const int lane = tid & 31;
    const int mw = wid & 1;          // m position: rows mw*16 within 32-row tile
    const int nq = wid >> 1;         // e quadrant: cols nq*32
    const int i = blockIdx.y;
    const int jh = blockIdx.x;       // 0/1 j-half

    if (tid < D) r_s[tid] = g_right[i * D + tid];
    __syncthreads();

    // ---- build B tile in smem (threads 0..127) + lin ----
    if (tid < E) {
        const int e = tid;
        float acc = 0.0f;
        alignas(16) __half hi[D];
        #pragma unroll
        for (int d = 0; d < D; ++d) {
            const float w1 = wo[d * E + e];
            const float w2 = wo[(D + d) * E + e];
            const float rd = r_s[d];
            hi[d] = __float2half_rn(fmaf(rd, w1, w2));
            acc = fmaf(rd, w2, acc);
        }
        lin_s[e] = bo[e] - acc;
        const uint4* h4 = reinterpret_cast<const uint4*>(hi);
        char* rowp = smem + SOFF_B + e * RSTRIDE;
        #pragma unroll
        for (int c = 0; c < 4; ++c)
            *reinterpret_cast<uint4*>(rowp + c * 16) = h4[c];
    }

    // ---- first A tile (32 rows) via cp.async into buffer 0 ----
    const __half* gA = g_lh;
    const int jbase = jh * 384;
    if (tid < 128) {
        const int row = tid >> 2, c = tid & 3;
        CP_ASYNC16(sb + SOFF_A0 + row * RSTRIDE + c * 16,
                   (const char*)(gA + (jbase + row) * D) + c * 16);
    }
    CP_COMMIT();
    CP_WAIT0();
    __syncthreads();

    // ---- hoist B fragments (32 cols per warp, both k-tiles) ----
    uint32_t bfr[2][4][2];
    #pragma unroll
    for (int kt = 0; kt < 2; ++kt) {
        #pragma unroll
        for (int p = 0; p < 2; ++p) {
            const uint32_t er = nq * 32 + p * 16;
            const uint32_t row = er + (lane & 7) + ((lane >> 4) << 3);
            const uint32_t addr = sB + row * RSTRIDE + kt * 32 + (((lane >> 3) & 1) << 4);
            uint32_t r[4];
            ldsm_x4(r, addr);
            bfr[kt][2 * p][0] = r[0]; bfr[kt][2 * p][1] = r[1];
            bfr[kt][2 * p + 1][0] = r[2]; bfr[kt][2 * p + 1][1] = r[3];
        }
    }

    // per-lane lin float4 (cols lane*4..lane*4+3, for STG phase)
    const float4 lreg = reinterpret_cast<const float4*>(lin_s)[lane];

    for (int jt = 0; jt < 12; ++jt) {
        const int j0 = jbase + jt * 32;
        const uint32_t sA = sb + ((jt & 1) ? SOFF_A1 : SOFF_A0);
        const uint32_t sAnext = sb + ((jt & 1) ? SOFF_A0 : SOFF_A1);

        // ---- mainloop: 2 k-tiles of 16 ----
        float acc[4][4];
        #pragma unroll
        for (int n = 0; n < 4; ++n)
            #pragma unroll
            for (int q = 0; q < 4; ++q) acc[n][q] = 0.0f;

        #pragma unroll
        for (int kt = 0; kt < 2; ++kt) {
            const uint32_t jr = mw * 16 + (lane & 15);
            const uint32_t addr = sA + jr * RSTRIDE + kt * 32 + ((lane >> 4) << 4);
            uint32_t a[4];
            ldsm_x4(a, addr);
            #pragma unroll
            for (int n = 0; n < 4; ++n)
                mma16816(acc[n], a, bfr[kt][n]);
        }

        // ---- prefetch next A tile (safe: targets the other buffer) ----
        const bool has_next = (jt < 11);
        if (has_next && tid < 128) {
            const int j1 = j0 + 32;
            const int row = tid >> 2, c = tid & 3;
            CP_ASYNC16(sAnext + row * RSTRIDE + c * 16,
                       (const char*)(gA + (j1 + row) * D) + c * 16);
        }
        if (has_next) CP_COMMIT();

        // ---- STS raw acc into swizzled stage (conflict-free) ----
        #pragma unroll
        for (int h = 0; h < 2; ++h) {
            const uint32_t r = mw * 16 + (lane >> 2) + 8 * h;
            const uint32_t rbase = sStage + r * 512 + ((lane & 1) << 3);
            const uint32_t sw = (r & 7) << 1;
            #pragma unroll
            for (int n = 0; n < 4; ++n) {
                const uint32_t chunk = nq * 8 + n * 2 + ((lane & 3) >> 1);
                const uint32_t addr = rbase + ((chunk ^ sw) << 4);
                asm volatile("st.shared.v2.f32 [%0], {%1,%2};"
                             :: "r"(addr), "f"(acc[n][2 * h]), "f"(acc[n][2 * h + 1]) : "memory");
            }
        }
        __syncthreads();

        // ---- drain: each warp owns 4 rows; one STG.128 writes a full 512B row ----
        #pragma unroll
        for (int rr = 0; rr < 4; ++rr) {
            const uint32_t r2 = wid * 4 + rr;
            const uint32_t la = sStage + r2 * 512 + (((uint32_t)lane ^ ((r2 & 7) << 1)) << 4);
            float v0, v1, v2, v3;
            asm volatile("ld.shared.v4.f32 {%0,%1,%2,%3}, [%4];"
                         : "=f"(v0), "=f"(v1), "=f"(v2), "=f"(v3) : "r"(la));
            float4 v;
            v.x = v0 + lreg.x; v.y = v1 + lreg.y; v.z = v2 + lreg.z; v.w = v3 + lreg.w;
            *reinterpret_cast<float4*>(out + ((size_t)i * L + j0 + r2) * E + lane * 4) = v;
        }

        if (has_next) CP_WAIT0();
        __syncthreads();
    }
}

// ---------------- launch ----------------
extern "C" void kernel_launch(void* const* d_in, const int* in_sizes, int n_in,
                              void* d_out, int out_size)
{
    const float* act  = (const float*)d_in[0];
    const float* mask = (const float*)d_in[1];
    const float* nw   = (const float*)d_in[2];
    const float* nb   = (const float*)d_in[3];
    const float* wl   = (const float*)d_in[4];
    const float* bl   = (const float*)d_in[5];
    const float* wr   = (const float*)d_in[6];
    const float* br   = (const float*)d_in[7];
    const float* wo   = (const float*)d_in[8];
    const float* bo   = (const float*)d_in[9];
    float* out = (float*)d_out;

    cudaFuncSetAttribute(pair_kernel, cudaFuncAttributeMaxDynamicSharedMemorySize, SMEM_PAIR);

    ln_proj_kernel<<<L, 256>>>(act, mask, nw, nb, wl, bl, wr, br);
    pair_kernel<<<dim3(2, L), 256, SMEM_PAIR>>>(wo, bo, out);
}

// round 13
// speedup vs baseline: 1.0034x; 1.0034x over previous
#include <cuda_runtime.h>
#include <cuda_fp16.h>
#include <cstdint>

// Problem constants (B=1)
#define L 768
#define C_IN 384
#define D 32          // C_OUTER
#define E 128         // C_OUT
#define EPS 1e-5f

// ---------------- scratch (no allocations allowed) ----------------
__device__ float g_right[L * D];
__device__ __align__(16) __half g_lh[L * D];   // left (fp16)

// ================= PTX helpers =================
__device__ __forceinline__ uint32_t smem_u32(const void* p) {
    uint32_t a;
    asm("{ .reg .u64 t; cvta.to.shared.u64 t, %1; cvt.u32.u64 %0, t; }" : "=r"(a) : "l"(p));
    return a;
}
__device__ __forceinline__ void ldsm_x4(uint32_t* r, uint32_t addr) {
    asm volatile("ldmatrix.sync.aligned.m8n8.x4.shared.b16 {%0,%1,%2,%3}, [%4];"
                 : "=r"(r[0]), "=r"(r[1]), "=r"(r[2]), "=r"(r[3]) : "r"(addr));
}
__device__ __forceinline__ void mma16816(float* c, const uint32_t* a, const uint32_t* b) {
    asm volatile("mma.sync.aligned.m16n8k16.row.col.f32.f16.f16.f32 "
                 "{%0,%1,%2,%3}, {%4,%5,%6,%7}, {%8,%9}, {%0,%1,%2,%3};"
                 : "+f"(c[0]), "+f"(c[1]), "+f"(c[2]), "+f"(c[3])
                 : "r"(a[0]), "r"(a[1]), "r"(a[2]), "r"(a[3]), "r"(b[0]), "r"(b[1]));
}
#define CP_ASYNC16(dst, src) \
    asm volatile("cp.async.ca.shared.global [%0], [%1], 16;" :: "r"(dst), "l"(src) : "memory")
#define CP_COMMIT()  asm volatile("cp.async.commit_group;" ::: "memory")
#define CP_WAIT0()   asm volatile("cp.async.wait_group 0;" ::: "memory")

// ---------------- Kernel A: LayerNorm + left/right projections ----------------
__global__ void __launch_bounds__(256) ln_proj_kernel(
    const float* __restrict__ act, const float* __restrict__ mask,
    const float* __restrict__ nw, const float* __restrict__ nb,
    const float* __restrict__ wl, const float* __restrict__ bl,
    const float* __restrict__ wr, const float* __restrict__ br)
{
    __shared__ float s_norm[C_IN];
    __shared__ float warp_sum[8];
    __shared__ float bcast;
    __shared__ float red[256];

    const int l = blockIdx.x;
    const int tid = threadIdx.x;
    const int lane = tid & 31;
    const int wid = tid >> 5;
    const float* arow = act + (size_t)l * C_IN;

    const float x0 = arow[tid];
    const float x1 = (tid < C_IN - 256) ? arow[256 + tid] : 0.0f;

    float s = x0 + x1;
    #pragma unroll
    for (int o = 16; o > 0; o >>= 1) s += __shfl_xor_sync(0xffffffffu, s, o);
    if (lane == 0) warp_sum[wid] = s;
    __syncthreads();
    if (tid == 0) {
        float t = 0.f;
        #pragma unroll
        for (int w = 0; w < 8; ++w) t += warp_sum[w];
        bcast = t * (1.0f / C_IN);
    }
    __syncthreads();
    const float mu = bcast;

    const float d0 = x0 - mu;
    const float d1 = (tid < C_IN - 256) ? (x1 - mu) : 0.0f;
    float v = d0 * d0 + d1 * d1;
    #pragma unroll
    for (int o = 16; o > 0; o >>= 1) v += __shfl_xor_sync(0xffffffffu, v, o);
    if (lane == 0) warp_sum[wid] = v;
    __syncthreads();
    if (tid == 0) {
        float t = 0.f;
        #pragma unroll
        for (int w = 0; w < 8; ++w) t += warp_sum[w];
        bcast = rsqrtf(t * (1.0f / C_IN) + EPS);
    }
    __syncthreads();
    const float rstd = bcast;

    s_norm[tid] = d0 * rstd * nw[tid] + nb[tid];
    if (tid < C_IN - 256)
        s_norm[256 + tid] = d1 * rstd * nw[256 + tid] + nb[256 + tid];
    __syncthreads();

    const int oc  = tid & 63;
    const int q   = tid >> 6;
    const int col = oc & 31;
    const float* w = (oc < 32) ? wl : wr;
    float dot = 0.0f;
    const int c0 = q * (C_IN / 4);
    #pragma unroll 8
    for (int c = c0; c < c0 + C_IN / 4; ++c)
        dot += s_norm[c] * w[c * D + col];
    red[tid] = dot;
    __syncthreads();
    if (tid < 128) red[tid] += red[tid + 128];
    __syncthreads();
    if (tid < 64) {
        const float vv = red[tid] + red[tid + 64];
        const float m = mask[l];
        const float val = m * (vv + ((oc < 32) ? bl[col] : br[col]));
        if (oc < 32) g_lh[l * D + col] = __float2half_rn(val);
        else         g_right[l * D + col] = val;
    }
}

// ---------------- Kernel C: mma.sync batched GEMM (fp16, K=32) ----------------
// grid = (2 j-halves, L i), block = 256 (8 warps: 2 mw x 4 nq), 12 j-tiles of 32 rows
// A double-buffered via cp.async; B fragments hoisted; output staged through a
// DOUBLE-BUFFERED swizzled smem stage -> ONE __syncthreads per tile.
#define RSTRIDE 80
#define BTILEB  10240
#define ATILEB  2560           // 32 rows x 80 B
#define STAGEB  16384          // 32 rows x 512 B
#define SOFF_LIN   0
#define SOFF_B     512
#define SOFF_A0    (512 + BTILEB)
#define SOFF_A1    (512 + BTILEB + ATILEB)
#define SOFF_STG   (512 + BTILEB + 2 * ATILEB)       // 15872
#define SMEM_PAIR  (SOFF_STG + 2 * STAGEB)           // 48640

__global__ void __launch_bounds__(256, 4) pair_kernel(
    const float* __restrict__ wo, const float* __restrict__ bo,
    float* __restrict__ out)
{
    extern __shared__ char smem[];
    __shared__ float r_s[D];
    const uint32_t sb = smem_u32(smem);
    const uint32_t sB = sb + SOFF_B;
    float* lin_s = reinterpret_cast<float*>(smem + SOFF_LIN);

    const int tid = threadIdx.x;
    const int wid = tid >> 5;
    const int lane = tid & 31;
    const int mw = wid & 1;          // m position: rows mw*16 within 32-row tile
    const int nq = wid >> 1;         // e quadrant: cols nq*32
    const int i = blockIdx.y;
    const int jh = blockIdx.x;       // 0/1 j-half

    if (tid < D) r_s[tid] = g_right[i * D + tid];
    __syncthreads();

    // ---- build B tile in smem (threads 0..127) + lin ----
    if (tid < E) {
        const int e = tid;
        float acc = 0.0f;
        alignas(16) __half hi[D];
        #pragma unroll
        for (int d = 0; d < D; ++d) {
            const float w1 = wo[d * E + e];
            const float w2 = wo[(D + d) * E + e];
            const float rd = r_s[d];
            hi[d] = __float2half_rn(fmaf(rd, w1, w2));
            acc = fmaf(rd, w2, acc);
        }
        lin_s[e] = bo[e] - acc;
        const uint4* h4 = reinterpret_cast<const uint4*>(hi);
        char* rowp = smem + SOFF_B + e * RSTRIDE;
        #pragma unroll
        for (int c = 0; c < 4; ++c)
            *reinterpret_cast<uint4*>(rowp + c * 16) = h4[c];
    }

    // ---- first A tile (32 rows) via cp.async into buffer 0 ----
    const __half* gA = g_lh;
    const int jbase = jh * 384;
    if (tid < 128) {
        const int row = tid >> 2, c = tid & 3;
        CP_ASYNC16(sb + SOFF_A0 + row * RSTRIDE + c * 16,
                   (const char*)(gA + (jbase + row) * D) + c * 16);
    }
    CP_COMMIT();
    CP_WAIT0();
    __syncthreads();

    // ---- hoist B fragments (32 cols per warp, both k-tiles) ----
    uint32_t bfr[2][4][2];
    #pragma unroll
    for (int kt = 0; kt < 2; ++kt) {
        #pragma unroll
        for (int p = 0; p < 2; ++p) {
            const uint32_t er = nq * 32 + p * 16;
            const uint32_t row = er + (lane & 7) + ((lane >> 4) << 3);
            const uint32_t addr = sB + row * RSTRIDE + kt * 32 + (((lane >> 3) & 1) << 4);
            uint32_t r[4];
            ldsm_x4(r, addr);
            bfr[kt][2 * p][0] = r[0]; bfr[kt][2 * p][1] = r[1];
            bfr[kt][2 * p + 1][0] = r[2]; bfr[kt][2 * p + 1][1] = r[3];
        }
    }

    // per-lane lin float4 (cols lane*4..lane*4+3, for STG phase)
    const float4 lreg = reinterpret_cast<const float4*>(lin_s)[lane];

    for (int jt = 0; jt < 12; ++jt) {
        const int j0 = jbase + jt * 32;
        const uint32_t sA     = sb + ((jt & 1) ? SOFF_A1 : SOFF_A0);
        const uint32_t sAnext = sb + ((jt & 1) ? SOFF_A0 : SOFF_A1);
        const uint32_t sStage = sb + SOFF_STG + ((jt & 1) ? STAGEB : 0);

        // ---- mainloop: 2 k-tiles of 16 ----
        float acc[4][4];
        #pragma unroll
        for (int n = 0; n < 4; ++n)
            #pragma unroll
            for (int q = 0; q < 4; ++q) acc[n][q] = 0.0f;

        #pragma unroll
        for (int kt = 0; kt < 2; ++kt) {
            const uint32_t jr = mw * 16 + (lane & 15);
            const uint32_t addr = sA + jr * RSTRIDE + kt * 32 + ((lane >> 4) << 4);
            uint32_t a[4];
            ldsm_x4(a, addr);
            #pragma unroll
            for (int n = 0; n < 4; ++n)
                mma16816(acc[n], a, bfr[kt][n]);
        }

        // ---- prefetch next A tile immediately (latency hidden under STS) ----
        const bool has_next = (jt < 11);
        if (has_next) {
            if (tid < 128) {
                const int j1 = j0 + 32;
                const int row = tid >> 2, c = tid & 3;
                CP_ASYNC16(sAnext + row * RSTRIDE + c * 16,
                           (const char*)(gA + (j1 + row) * D) + c * 16);
            }
            CP_COMMIT();
        }

        // ---- STS raw acc into this tile's stage buffer (conflict-free) ----
        #pragma unroll
        for (int h = 0; h < 2; ++h) {
            const uint32_t r = mw * 16 + (lane >> 2) + 8 * h;
            const uint32_t rbase = sStage + r * 512 + ((lane & 1) << 3);
            const uint32_t sw = (r & 7) << 1;
            #pragma unroll
            for (int n = 0; n < 4; ++n) {
                const uint32_t chunk = nq * 8 + n * 2 + ((lane & 3) >> 1);
                const uint32_t addr = rbase + ((chunk ^ sw) << 4);
                asm volatile("st.shared.v2.f32 [%0], {%1,%2};"
                             :: "r"(addr), "f"(acc[n][2 * h]), "f"(acc[n][2 * h + 1]) : "memory");
            }
        }

        if (has_next) CP_WAIT0();
        __syncthreads();   // single barrier: stage visible + next A ready

        // ---- drain: each warp owns 4 rows; one STG.128 writes a full 512B row ----
        #pragma unroll
        for (int rr = 0; rr < 4; ++rr) {
            const uint32_t r2 = wid * 4 + rr;
            const uint32_t la = sStage + r2 * 512 + (((uint32_t)lane ^ ((r2 & 7) << 1)) << 4);
            float v0, v1, v2, v3;
            asm volatile("ld.shared.v4.f32 {%0,%1,%2,%3}, [%4];"
                         : "=f"(v0), "=f"(v1), "=f"(v2), "=f"(v3) : "r"(la));
            float4 v;
            v.x = v0 + lreg.x; v.y = v1 + lreg.y; v.z = v2 + lreg.z; v.w = v3 + lreg.w;
            *reinterpret_cast<float4*>(out + ((size_t)i * L + j0 + r2) * E + lane * 4) = v;
        }
    }
}

// ---------------- launch ----------------
extern "C" void kernel_launch(void* const* d_in, const int* in_sizes, int n_in,
                              void* d_out, int out_size)
{
    const float* act  = (const float*)d_in[0];
    const float* mask = (const float*)d_in[1];
    const float* nw   = (const float*)d_in[2];
    const float* nb   = (const float*)d_in[3];
    const float* wl   = (const float*)d_in[4];
    const float* bl   = (const float*)d_in[5];
    const float* wr   = (const float*)d_in[6];
    const float* br   = (const float*)d_in[7];
    const float* wo   = (const float*)d_in[8];
    const float* bo   = (const float*)d_in[9];
    float* out = (float*)d_out;

    cudaFuncSetAttribute(pair_kernel, cudaFuncAttributeMaxDynamicSharedMemorySize, SMEM_PAIR);

    ln_proj_kernel<<<L, 256>>>(act, mask, nw, nb, wl, bl, wr, br);
    pair_kernel<<<dim3(2, L), 256, SMEM_PAIR>>>(wo, bo, out);
}